// round 3
// baseline (speedup 1.0000x reference)
#include <cuda_runtime.h>
#include <math.h>
#include <stdint.h>

#define BB      8
#define NHEADS  8
#define HD      32
#define NN      1024
#define CDIM    256
#define TABLE_SZ 3969
#define CPBH    512

// ---------------- scratch ------------------------------------------------
__device__ float g_qkv[BB * NN * 3 * CDIM];
__device__ float g_qs [BB * NHEADS * NN * HD];
__device__ float g_kn [BB * NHEADS * NN * HD];
__device__ float g_v  [BB * NHEADS * NN * HD];
__device__ float g_tab[NHEADS * TABLE_SZ];
__device__ float g_ao [BB * NN * CDIM];

// ---------------- tf32 helpers -------------------------------------------
__device__ __forceinline__ void tf32x2(float x, uint32_t &hi, uint32_t &lo) {
    uint32_t h;
    asm("cvt.rna.tf32.f32 %0, %1;" : "=r"(h) : "f"(x));
    float rem = x - __uint_as_float(h);
    uint32_t l;
    asm("cvt.rna.tf32.f32 %0, %1;" : "=r"(l) : "f"(rem));
    hi = h; lo = l;
}

__device__ __forceinline__ uint32_t tf32_1(float x) {
    uint32_t h;
    asm("cvt.rna.tf32.f32 %0, %1;" : "=r"(h) : "f"(x));
    return h;
}

__device__ __forceinline__ void mma_tf32(float c[4],
                                         uint32_t a0, uint32_t a1, uint32_t a2, uint32_t a3,
                                         uint32_t b0, uint32_t b1) {
    asm volatile(
        "mma.sync.aligned.m16n8k8.row.col.f32.tf32.tf32.f32 "
        "{%0,%1,%2,%3}, {%4,%5,%6,%7}, {%8,%9}, {%0,%1,%2,%3};"
        : "+f"(c[0]), "+f"(c[1]), "+f"(c[2]), "+f"(c[3])
        : "r"(a0), "r"(a1), "r"(a2), "r"(a3), "r"(b0), "r"(b1));
}

// ---------------- CPB MLP -------------------------------------------------
__global__ void cpb_kernel(const float* __restrict__ coords,
                           const float* __restrict__ fc1w, const float* __restrict__ fc1b,
                           const float* __restrict__ fc2w, const float* __restrict__ fc2b) {
    int t = blockIdx.x;
    float c0 = coords[t * 2 + 0];
    float c1 = coords[t * 2 + 1];
    float acc[NHEADS];
#pragma unroll
    for (int h = 0; h < NHEADS; h++) acc[h] = 0.f;
    for (int j = threadIdx.x; j < CPBH; j += blockDim.x) {
        float hv = fmaxf(c0 * fc1w[j * 2] + c1 * fc1w[j * 2 + 1] + fc1b[j], 0.f);
#pragma unroll
        for (int h = 0; h < NHEADS; h++) acc[h] += hv * fc2w[h * CPBH + j];
    }
    __shared__ float red[4][NHEADS];
    int lane = threadIdx.x & 31, warp = threadIdx.x >> 5;
#pragma unroll
    for (int h = 0; h < NHEADS; h++)
        for (int o = 16; o; o >>= 1) acc[h] += __shfl_xor_sync(0xffffffffu, acc[h], o);
    if (lane == 0)
#pragma unroll
        for (int h = 0; h < NHEADS; h++) red[warp][h] = acc[h];
    __syncthreads();
    if (threadIdx.x < NHEADS) {
        float s = fc2b[threadIdx.x];
        for (int w = 0; w < 4; w++) s += red[w][threadIdx.x];
        g_tab[threadIdx.x * TABLE_SZ + t] = s;
    }
}

// ---------------- 3xTF32 GEMM, 128x64 tile, 256 threads --------------------
// hi/lo split done once per SMEM tile; fragments are clean LDS.64.
// warps: 4 rows x 2 cols, warp tile 32x32.
__global__ void __launch_bounds__(256) gemm_tc(const float* __restrict__ A,
                                               const float* __restrict__ W,
                                               const float* __restrict__ bias,
                                               float* __restrict__ C,
                                               int M, int N, int K) {
    extern __shared__ uint2 smg[];
    uint2* As = smg;                 // [128][36] uint2 (hi,lo)
    uint2* Ws = smg + 128 * 36;      // [64][36]
    const int bm = blockIdx.y * 128, bn = blockIdx.x * 64;
    const int tid = threadIdx.x, lane = tid & 31, warp = tid >> 5;
    const int wm = (warp >> 1) * 32, wn = (warp & 1) * 32;
    const int r = lane >> 2, c = lane & 3;

    float acc[2][4][4];
#pragma unroll
    for (int mt = 0; mt < 2; mt++)
#pragma unroll
        for (int nt = 0; nt < 4; nt++)
#pragma unroll
            for (int q = 0; q < 4; q++) acc[mt][nt][q] = 0.f;

    for (int k0 = 0; k0 < K; k0 += 32) {
        // A: 128x32 = 1024 float4 slots / 256 threads = 4 iters
#pragma unroll
        for (int i = 0; i < 4; i++) {
            int v = tid + i * 256;
            int row = v >> 3, kq = (v & 7) * 4;
            float4 a4 = *(const float4*)&A[(size_t)(bm + row) * K + k0 + kq];
            uint2* dst = &As[row * 36 + kq];
            tf32x2(a4.x, dst[0].x, dst[0].y);
            tf32x2(a4.y, dst[1].x, dst[1].y);
            tf32x2(a4.z, dst[2].x, dst[2].y);
            tf32x2(a4.w, dst[3].x, dst[3].y);
        }
        // W: 64x32 = 512 slots / 256 = 2 iters
#pragma unroll
        for (int i = 0; i < 2; i++) {
            int v = tid + i * 256;
            int row = v >> 3, kq = (v & 7) * 4;
            float4 w4 = *(const float4*)&W[(size_t)(bn + row) * K + k0 + kq];
            uint2* dst = &Ws[row * 36 + kq];
            tf32x2(w4.x, dst[0].x, dst[0].y);
            tf32x2(w4.y, dst[1].x, dst[1].y);
            tf32x2(w4.z, dst[2].x, dst[2].y);
            tf32x2(w4.w, dst[3].x, dst[3].y);
        }
        __syncthreads();
#pragma unroll
        for (int kt = 0; kt < 4; kt++) {
            uint2 a0[2], a1[2], a2[2], a3[2];
#pragma unroll
            for (int mt = 0; mt < 2; mt++) {
                int rb = wm + mt * 16;
                a0[mt] = As[(rb + r)     * 36 + kt * 8 + c];
                a1[mt] = As[(rb + r + 8) * 36 + kt * 8 + c];
                a2[mt] = As[(rb + r)     * 36 + kt * 8 + 4 + c];
                a3[mt] = As[(rb + r + 8) * 36 + kt * 8 + 4 + c];
            }
#pragma unroll
            for (int nt = 0; nt < 4; nt++) {
                uint2 b0 = Ws[(wn + nt * 8 + r) * 36 + kt * 8 + c];
                uint2 b1 = Ws[(wn + nt * 8 + r) * 36 + kt * 8 + 4 + c];
#pragma unroll
                for (int mt = 0; mt < 2; mt++) {
                    mma_tf32(acc[mt][nt], a0[mt].x, a1[mt].x, a2[mt].x, a3[mt].x, b0.x, b1.x);
                    mma_tf32(acc[mt][nt], a0[mt].x, a1[mt].x, a2[mt].x, a3[mt].x, b0.y, b1.y);
                    mma_tf32(acc[mt][nt], a0[mt].y, a1[mt].y, a2[mt].y, a3[mt].y, b0.x, b1.x);
                }
            }
        }
        __syncthreads();
    }
#pragma unroll
    for (int mt = 0; mt < 2; mt++) {
        int row0 = bm + wm + mt * 16 + r;
        int row1 = row0 + 8;
#pragma unroll
        for (int nt = 0; nt < 4; nt++) {
            int n = bn + wn + nt * 8 + 2 * c;
            float b0 = bias[n], b1 = bias[n + 1];
            *(float2*)&C[(size_t)row0 * N + n] = make_float2(acc[mt][nt][0] + b0, acc[mt][nt][1] + b1);
            *(float2*)&C[(size_t)row1 * N + n] = make_float2(acc[mt][nt][2] + b0, acc[mt][nt][3] + b1);
        }
    }
}

// ---------------- prep ----------------------------------------------------
__global__ void prep_kernel(const float* __restrict__ qe, const float* __restrict__ temp) {
    int gtid = blockIdx.x * blockDim.x + threadIdx.x;
    int w = gtid >> 5;
    int lane = gtid & 31;
    if (w >= BB * NHEADS * NN) return;
    int n = w % NN;
    int h = (w / NN) % NHEADS;
    int b = w / (NN * NHEADS);
    size_t row = (size_t)(b * NN + n) * (3 * CDIM);
    float q = g_qkv[row + h * HD + lane];
    float k = g_qkv[row + CDIM + h * HD + lane];
    float v = g_qkv[row + 2 * CDIM + h * HD + lane];
    float q2 = q * q, k2 = k * k;
#pragma unroll
    for (int o = 16; o; o >>= 1) {
        q2 += __shfl_xor_sync(0xffffffffu, q2, o);
        k2 += __shfl_xor_sync(0xffffffffu, k2, o);
    }
    float qn = q / fmaxf(sqrtf(q2), 1e-12f) + qe[h * HD + lane];
    float kn = k / fmaxf(sqrtf(k2), 1e-12f);
    float scale = log1pf(expf(temp[h])) * logf(1024.0f);
    size_t o = (size_t)w * HD + lane;
    g_qs[o] = qn * scale;
    g_kn[o] = kn;
    g_v[o]  = v;
}

// ---------------- tensor-core flash attention ------------------------------
// grid (16, H, B), 128 threads (4 warps), 64 q-rows/block, 16 rows/warp.
// K/V split to tf32 hi/lo at tile-load time (uint2 SMEM). P truncated to
// tf32 (single plane); PV = Ph*Vh + Ph*Vl (2 mmas).
__global__ void __launch_bounds__(128, 3) attn_tc(const int* __restrict__ rpi,
                                                  float* __restrict__ out) {
    extern __shared__ float sm[];
    float* tab_s = sm;                          // 3972
    uint2* K_s   = (uint2*)(tab_s + 3972);      // [64][36] (hi,lo)
    uint2* V_s   = K_s + 64 * 36;               // [64][36]
    float* P_s   = (float*)(V_s + 64 * 36);     // [64][72]  (also Q staging)

    const int n0 = blockIdx.x * 64;
    const int h  = blockIdx.y;
    const int b  = blockIdx.z;
    const int tid = threadIdx.x, lane = tid & 31, warp = tid >> 5;
    const int r = lane >> 2, c = lane & 3;

    for (int i = tid; i < TABLE_SZ; i += 128) tab_s[i] = g_tab[h * TABLE_SZ + i];

    // stage Q into P_s, build register-resident Q fragments (hi/lo)
    const float* qbase = g_qs + ((size_t)(b * NHEADS + h) * NN + n0) * HD;
#pragma unroll
    for (int i = 0; i < 16; i++) {
        int e = tid + i * 128;
        P_s[(e >> 5) * 72 + (e & 31)] = qbase[e];
    }
    __syncthreads();
    uint32_t qh[4][4], ql[4][4];
    {
        int rb = warp * 16;
#pragma unroll
        for (int ks = 0; ks < 4; ks++) {
            tf32x2(P_s[(rb + r)     * 72 + ks * 8 + c],     qh[ks][0], ql[ks][0]);
            tf32x2(P_s[(rb + r + 8) * 72 + ks * 8 + c],     qh[ks][1], ql[ks][1]);
            tf32x2(P_s[(rb + r)     * 72 + ks * 8 + 4 + c], qh[ks][2], ql[ks][2]);
            tf32x2(P_s[(rb + r + 8) * 72 + ks * 8 + 4 + c], qh[ks][3], ql[ks][3]);
        }
    }

    float O[4][4] = {};
    float ml0 = -1e30f, ml1 = -1e30f, ll0 = 0.f, ll1 = 0.f;
    const float* kbase = g_kn + (size_t)(b * NHEADS + h) * NN * HD;
    const float* vbase = g_v  + (size_t)(b * NHEADS + h) * NN * HD;
    const int*   rbase = rpi + (size_t)(n0 + warp * 16) * NN;

    for (int kt = 0; kt < 16; kt++) {
        __syncthreads();   // prior tile fully consumed (also guards Q staging)
        // cooperative K/V load + hi/lo split: 512 float4 slots
#pragma unroll
        for (int i = 0; i < 4; i++) {
            int v = tid + i * 128;
            int m = v >> 3, d0 = (v & 7) * 4;
            float4 kf = *(const float4*)&kbase[kt * 2048 + m * 32 + d0];
            float4 vf = *(const float4*)&vbase[kt * 2048 + m * 32 + d0];
            uint2* kd = &K_s[m * 36 + d0];
            uint2* vd = &V_s[m * 36 + d0];
            tf32x2(kf.x, kd[0].x, kd[0].y);
            tf32x2(kf.y, kd[1].x, kd[1].y);
            tf32x2(kf.z, kd[2].x, kd[2].y);
            tf32x2(kf.w, kd[3].x, kd[3].y);
            tf32x2(vf.x, vd[0].x, vd[0].y);
            tf32x2(vf.y, vd[1].x, vd[1].y);
            tf32x2(vf.z, vd[2].x, vd[2].y);
            tf32x2(vf.w, vd[3].x, vd[3].y);
        }
        __syncthreads();

        // ---- S = Q K^T + bias ----
        float sc[8][4];
#pragma unroll
        for (int j = 0; j < 8; j++) {
            int colb = kt * 64 + j * 8 + 2 * c;
            int2 ia = *(const int2*)&rbase[(size_t)r       * NN + colb];
            int2 ib = *(const int2*)&rbase[(size_t)(r + 8) * NN + colb];
            sc[j][0] = tab_s[ia.x]; sc[j][1] = tab_s[ia.y];
            sc[j][2] = tab_s[ib.x]; sc[j][3] = tab_s[ib.y];
#pragma unroll
            for (int ks = 0; ks < 4; ks++) {
                uint2 kb0 = K_s[(j * 8 + r) * 36 + ks * 8 + c];
                uint2 kb1 = K_s[(j * 8 + r) * 36 + ks * 8 + 4 + c];
                mma_tf32(sc[j], qh[ks][0], qh[ks][1], qh[ks][2], qh[ks][3], kb0.x, kb1.x);
                mma_tf32(sc[j], qh[ks][0], qh[ks][1], qh[ks][2], qh[ks][3], kb0.y, kb1.y);
                mma_tf32(sc[j], ql[ks][0], ql[ks][1], ql[ks][2], ql[ks][3], kb0.x, kb1.x);
            }
        }

        // ---- online softmax (thread owns rows r and r+8 of warp tile) ----
        float mx0 = -1e30f, mx1 = -1e30f;
#pragma unroll
        for (int j = 0; j < 8; j++) {
            mx0 = fmaxf(mx0, fmaxf(sc[j][0], sc[j][1]));
            mx1 = fmaxf(mx1, fmaxf(sc[j][2], sc[j][3]));
        }
        mx0 = fmaxf(mx0, __shfl_xor_sync(0xffffffffu, mx0, 1));
        mx0 = fmaxf(mx0, __shfl_xor_sync(0xffffffffu, mx0, 2));
        mx1 = fmaxf(mx1, __shfl_xor_sync(0xffffffffu, mx1, 1));
        mx1 = fmaxf(mx1, __shfl_xor_sync(0xffffffffu, mx1, 2));
        float mn0 = fmaxf(ml0, mx0), mn1 = fmaxf(ml1, mx1);
        float a0 = __expf(ml0 - mn0), a1 = __expf(ml1 - mn1);
        float s0 = 0.f, s1 = 0.f;
        float* prow0 = &P_s[(warp * 16 + r)     * 72];
        float* prow1 = &P_s[(warp * 16 + r + 8) * 72];
#pragma unroll
        for (int j = 0; j < 8; j++) {
            // truncate P to tf32 so l-sum matches the PV operand exactly
            float p0 = __uint_as_float(tf32_1(__expf(sc[j][0] - mn0)));
            float p1 = __uint_as_float(tf32_1(__expf(sc[j][1] - mn0)));
            float p2 = __uint_as_float(tf32_1(__expf(sc[j][2] - mn1)));
            float p3 = __uint_as_float(tf32_1(__expf(sc[j][3] - mn1)));
            s0 += p0 + p1; s1 += p2 + p3;
            *(float2*)&prow0[j * 8 + 2 * c] = make_float2(p0, p1);
            *(float2*)&prow1[j * 8 + 2 * c] = make_float2(p2, p3);
        }
        s0 += __shfl_xor_sync(0xffffffffu, s0, 1);
        s0 += __shfl_xor_sync(0xffffffffu, s0, 2);
        s1 += __shfl_xor_sync(0xffffffffu, s1, 1);
        s1 += __shfl_xor_sync(0xffffffffu, s1, 2);
        ll0 = ll0 * a0 + s0; ll1 = ll1 * a1 + s1;
        ml0 = mn0; ml1 = mn1;
#pragma unroll
        for (int jd = 0; jd < 4; jd++) {
            O[jd][0] *= a0; O[jd][1] *= a0;
            O[jd][2] *= a1; O[jd][3] *= a1;
        }
        __syncwarp();   // P rows are warp-private; order stores vs loads

        // ---- O += P @ V  (Ph*Vh + Ph*Vl) ----
#pragma unroll
        for (int kk = 0; kk < 8; kk++) {
            uint32_t ah0 = __float_as_uint(P_s[(warp * 16 + r)     * 72 + kk * 8 + c]);
            uint32_t ah1 = __float_as_uint(P_s[(warp * 16 + r + 8) * 72 + kk * 8 + c]);
            uint32_t ah2 = __float_as_uint(P_s[(warp * 16 + r)     * 72 + kk * 8 + 4 + c]);
            uint32_t ah3 = __float_as_uint(P_s[(warp * 16 + r + 8) * 72 + kk * 8 + 4 + c]);
#pragma unroll
            for (int jd = 0; jd < 4; jd++) {
                uint2 v0 = V_s[(kk * 8 + c)     * 36 + jd * 8 + r];
                uint2 v1 = V_s[(kk * 8 + 4 + c) * 36 + jd * 8 + r];
                mma_tf32(O[jd], ah0, ah1, ah2, ah3, v0.x, v1.x);
                mma_tf32(O[jd], ah0, ah1, ah2, ah3, v0.y, v1.y);
            }
        }
    }

    // ---- epilogue: normalize + write [b][n][h*32+d] ----
    float i0 = 1.f / ll0, i1 = 1.f / ll1;
    int row0 = n0 + warp * 16 + r;
    int row1 = row0 + 8;
#pragma unroll
    for (int jd = 0; jd < 4; jd++) {
        int col = h * HD + jd * 8 + 2 * c;
        *(float2*)&out[(size_t)(b * NN + row0) * CDIM + col] =
            make_float2(O[jd][0] * i0, O[jd][1] * i0);
        *(float2*)&out[(size_t)(b * NN + row1) * CDIM + col] =
            make_float2(O[jd][2] * i1, O[jd][3] * i1);
    }
}

// ---------------- launch ----------------------------------------------------
extern "C" void kernel_launch(void* const* d_in, const int* in_sizes, int n_in,
                              void* d_out, int out_size) {
    int s = (n_in >= 15) ? 0 : -2;
    const float* x       = (const float*)d_in[0];
    const int*   rpi     = (const int*)  d_in[3 + s];
    const float* coords  = (const float*)d_in[4 + s];
    const float* qkv_w   = (const float*)d_in[5 + s];
    const float* qkv_b   = (const float*)d_in[6 + s];
    const float* qe      = (const float*)d_in[7 + s];
    const float* temp    = (const float*)d_in[8 + s];
    const float* proj_w  = (const float*)d_in[9 + s];
    const float* proj_b  = (const float*)d_in[10 + s];
    const float* fc1w    = (const float*)d_in[11 + s];
    const float* fc1b    = (const float*)d_in[12 + s];
    const float* fc2w    = (const float*)d_in[13 + s];
    const float* fc2b    = (const float*)d_in[14 + s];
    float* out = (float*)d_out;

    float *p_qkv, *p_ao;
    cudaGetSymbolAddress((void**)&p_qkv, g_qkv);
    cudaGetSymbolAddress((void**)&p_ao,  g_ao);

    cpb_kernel<<<TABLE_SZ, 128>>>(coords, fc1w, fc1b, fc2w, fc2b);

    size_t gemm_smem = (128 * 36 + 64 * 36) * sizeof(uint2);   // ~55.3 KB
    cudaFuncSetAttribute(gemm_tc, cudaFuncAttributeMaxDynamicSharedMemorySize, (int)gemm_smem);

    gemm_tc<<<dim3(768 / 64, (BB * NN) / 128), 256, gemm_smem>>>(
        x, qkv_w, qkv_b, p_qkv, BB * NN, 3 * CDIM, CDIM);

    {
        int warps = BB * NHEADS * NN;
        int threads = warps * 32;
        prep_kernel<<<(threads + 255) / 256, 256>>>(qe, temp);
    }

    {
        size_t smem = 3972 * 4 + 64 * 36 * 8 * 2 + 64 * 72 * 4;   // ~69.5 KB
        cudaFuncSetAttribute(attn_tc, cudaFuncAttributeMaxDynamicSharedMemorySize, (int)smem);
        attn_tc<<<dim3(16, NHEADS, BB), 128, smem>>>(rpi, p_ao);
    }

    gemm_tc<<<dim3(CDIM / 64, (BB * NN) / 128), 256, gemm_smem>>>(
        p_ao, proj_w, proj_b, out, BB * NN, CDIM, CDIM);
}

// round 4
// speedup vs baseline: 1.5946x; 1.5946x over previous
#include <cuda_runtime.h>
#include <math.h>
#include <stdint.h>

#define BB      8
#define NHEADS  8
#define HD      32
#define NN      1024
#define CDIM    256
#define TABLE_SZ 3969
#define CPBH    512

// ---------------- scratch ------------------------------------------------
__device__ float g_qkv[BB * NN * 3 * CDIM];
__device__ float g_qs [BB * NHEADS * NN * HD];
__device__ float g_kn [BB * NHEADS * NN * HD];
__device__ float g_v  [BB * NHEADS * NN * HD];
__device__ float g_tab[NHEADS * TABLE_SZ];
__device__ float g_ao [BB * NN * CDIM];

// ---------------- bf16 helpers --------------------------------------------
// pack(lo, hi): lo -> low 16 bits (first k element), hi -> high 16 bits
__device__ __forceinline__ uint32_t bf16x2(float lo, float hi) {
    uint32_t d;
    asm("cvt.rn.bf16x2.f32 %0, %1, %2;" : "=r"(d) : "f"(hi), "f"(lo));
    return d;
}
// split pair (x0 = even k, x1 = odd k) into hi-plane word + lo-plane word
__device__ __forceinline__ void bfsplit2(float x0, float x1, uint32_t &hi, uint32_t &lo) {
    uint32_t h = bf16x2(x0, x1);
    float r0 = x0 - __uint_as_float(h << 16);
    float r1 = x1 - __uint_as_float(h & 0xffff0000u);
    hi = h;
    lo = bf16x2(r0, r1);
}

__device__ __forceinline__ void mma_bf16(float c[4],
                                         uint32_t a0, uint32_t a1, uint32_t a2, uint32_t a3,
                                         uint32_t b0, uint32_t b1) {
    asm volatile(
        "mma.sync.aligned.m16n8k16.row.col.f32.bf16.bf16.f32 "
        "{%0,%1,%2,%3}, {%4,%5,%6,%7}, {%8,%9}, {%0,%1,%2,%3};"
        : "+f"(c[0]), "+f"(c[1]), "+f"(c[2]), "+f"(c[3])
        : "r"(a0), "r"(a1), "r"(a2), "r"(a3), "r"(b0), "r"(b1));
}

// ---------------- CPB MLP -------------------------------------------------
__global__ void cpb_kernel(const float* __restrict__ coords,
                           const float* __restrict__ fc1w, const float* __restrict__ fc1b,
                           const float* __restrict__ fc2w, const float* __restrict__ fc2b) {
    int t = blockIdx.x;
    float c0 = coords[t * 2 + 0];
    float c1 = coords[t * 2 + 1];
    float acc[NHEADS];
#pragma unroll
    for (int h = 0; h < NHEADS; h++) acc[h] = 0.f;
    for (int j = threadIdx.x; j < CPBH; j += blockDim.x) {
        float hv = fmaxf(c0 * fc1w[j * 2] + c1 * fc1w[j * 2 + 1] + fc1b[j], 0.f);
#pragma unroll
        for (int h = 0; h < NHEADS; h++) acc[h] += hv * fc2w[h * CPBH + j];
    }
    __shared__ float red[4][NHEADS];
    int lane = threadIdx.x & 31, warp = threadIdx.x >> 5;
#pragma unroll
    for (int h = 0; h < NHEADS; h++)
        for (int o = 16; o; o >>= 1) acc[h] += __shfl_xor_sync(0xffffffffu, acc[h], o);
    if (lane == 0)
#pragma unroll
        for (int h = 0; h < NHEADS; h++) red[warp][h] = acc[h];
    __syncthreads();
    if (threadIdx.x < NHEADS) {
        float s = fc2b[threadIdx.x];
        for (int w = 0; w < 4; w++) s += red[w][threadIdx.x];
        g_tab[threadIdx.x * TABLE_SZ + t] = s;
    }
}

// ---------------- 3xBF16 GEMM, 128x64 tile, 256 threads --------------------
// hi/lo bf16 planes built once per BK tile; fragments = conflict-free LDS.32.
// warps 4x2, warp tile 32x32, BK=32 (2 k16 steps).
__global__ void __launch_bounds__(256) gemm_tc(const float* __restrict__ A,
                                               const float* __restrict__ W,
                                               const float* __restrict__ bias,
                                               float* __restrict__ C,
                                               int M, int N, int K) {
    extern __shared__ uint32_t smg[];
    uint32_t* Ah = smg;               // [128][20]
    uint32_t* Al = Ah + 128 * 20;
    uint32_t* Wh = Al + 128 * 20;     // [64][20]
    uint32_t* Wl = Wh + 64 * 20;
    const int bm = blockIdx.y * 128, bn = blockIdx.x * 64;
    const int tid = threadIdx.x, lane = tid & 31, warp = tid >> 5;
    const int wm = (warp >> 1) * 32, wn = (warp & 1) * 32;
    const int r = lane >> 2, c = lane & 3;

    float acc[2][4][4];
#pragma unroll
    for (int mt = 0; mt < 2; mt++)
#pragma unroll
        for (int nt = 0; nt < 4; nt++)
#pragma unroll
            for (int q = 0; q < 4; q++) acc[mt][nt][q] = 0.f;

    for (int k0 = 0; k0 < K; k0 += 32) {
#pragma unroll
        for (int i = 0; i < 4; i++) {
            int v = tid + i * 256;
            int row = v >> 3, kq = (v & 7) * 4;
            float4 a4 = *(const float4*)&A[(size_t)(bm + row) * K + k0 + kq];
            uint32_t h, l;
            bfsplit2(a4.x, a4.y, h, l);
            Ah[row * 20 + (kq >> 1)] = h;  Al[row * 20 + (kq >> 1)] = l;
            bfsplit2(a4.z, a4.w, h, l);
            Ah[row * 20 + (kq >> 1) + 1] = h;  Al[row * 20 + (kq >> 1) + 1] = l;
        }
#pragma unroll
        for (int i = 0; i < 2; i++) {
            int v = tid + i * 256;
            int row = v >> 3, kq = (v & 7) * 4;
            float4 w4 = *(const float4*)&W[(size_t)(bn + row) * K + k0 + kq];
            uint32_t h, l;
            bfsplit2(w4.x, w4.y, h, l);
            Wh[row * 20 + (kq >> 1)] = h;  Wl[row * 20 + (kq >> 1)] = l;
            bfsplit2(w4.z, w4.w, h, l);
            Wh[row * 20 + (kq >> 1) + 1] = h;  Wl[row * 20 + (kq >> 1) + 1] = l;
        }
        __syncthreads();
#pragma unroll
        for (int kt = 0; kt < 2; kt++) {
            uint32_t ah[2][4], al[2][4];
#pragma unroll
            for (int mt = 0; mt < 2; mt++) {
                int r0 = (wm + mt * 16 + r) * 20 + kt * 8 + c;
                int r1 = r0 + 8 * 20;
                ah[mt][0] = Ah[r0];     al[mt][0] = Al[r0];
                ah[mt][1] = Ah[r1];     al[mt][1] = Al[r1];
                ah[mt][2] = Ah[r0 + 4]; al[mt][2] = Al[r0 + 4];
                ah[mt][3] = Ah[r1 + 4]; al[mt][3] = Al[r1 + 4];
            }
#pragma unroll
            for (int nt = 0; nt < 4; nt++) {
                int w0 = (wn + nt * 8 + r) * 20 + kt * 8 + c;
                uint32_t bh0 = Wh[w0], bh1 = Wh[w0 + 4];
                uint32_t bl0 = Wl[w0], bl1 = Wl[w0 + 4];
#pragma unroll
                for (int mt = 0; mt < 2; mt++) {
                    mma_bf16(acc[mt][nt], ah[mt][0], ah[mt][1], ah[mt][2], ah[mt][3], bh0, bh1);
                    mma_bf16(acc[mt][nt], al[mt][0], al[mt][1], al[mt][2], al[mt][3], bh0, bh1);
                    mma_bf16(acc[mt][nt], ah[mt][0], ah[mt][1], ah[mt][2], ah[mt][3], bl0, bl1);
                }
            }
        }
        __syncthreads();
    }
#pragma unroll
    for (int mt = 0; mt < 2; mt++) {
        int row0 = bm + wm + mt * 16 + r;
        int row1 = row0 + 8;
#pragma unroll
        for (int nt = 0; nt < 4; nt++) {
            int n = bn + wn + nt * 8 + 2 * c;
            float b0 = bias[n], b1 = bias[n + 1];
            *(float2*)&C[(size_t)row0 * N + n] = make_float2(acc[mt][nt][0] + b0, acc[mt][nt][1] + b1);
            *(float2*)&C[(size_t)row1 * N + n] = make_float2(acc[mt][nt][2] + b0, acc[mt][nt][3] + b1);
        }
    }
}

// ---------------- prep ----------------------------------------------------
__global__ void prep_kernel(const float* __restrict__ qe, const float* __restrict__ temp) {
    int gtid = blockIdx.x * blockDim.x + threadIdx.x;
    int w = gtid >> 5;
    int lane = gtid & 31;
    if (w >= BB * NHEADS * NN) return;
    int n = w % NN;
    int h = (w / NN) % NHEADS;
    int b = w / (NN * NHEADS);
    size_t row = (size_t)(b * NN + n) * (3 * CDIM);
    float q = g_qkv[row + h * HD + lane];
    float k = g_qkv[row + CDIM + h * HD + lane];
    float v = g_qkv[row + 2 * CDIM + h * HD + lane];
    float q2 = q * q, k2 = k * k;
#pragma unroll
    for (int o = 16; o; o >>= 1) {
        q2 += __shfl_xor_sync(0xffffffffu, q2, o);
        k2 += __shfl_xor_sync(0xffffffffu, k2, o);
    }
    float qn = q / fmaxf(sqrtf(q2), 1e-12f) + qe[h * HD + lane];
    float kn = k / fmaxf(sqrtf(k2), 1e-12f);
    float scale = log1pf(expf(temp[h])) * logf(1024.0f);
    size_t o = (size_t)w * HD + lane;
    g_qs[o] = qn * scale;
    g_kn[o] = kn;
    g_v[o]  = v;
}

// ---------------- bf16 tensor-core flash attention --------------------------
// grid (16, H, B), 128 threads (4 warps), 64 q-rows/block, 16 rows/warp.
// K/V: bf16 hi/lo planes in SMEM (packed k-pairs, conflict-free pitches).
// P: register-chained bf16 hi/lo fragments, no SMEM round-trip.
__global__ void __launch_bounds__(128, 4) attn_tc(const int* __restrict__ rpi,
                                                  float* __restrict__ out) {
    extern __shared__ float sm[];
    float*    tab_s = sm;                              // 3972 words
    uint32_t* Kh = (uint32_t*)(sm + 3972);             // [64][20]
    uint32_t* Kl = Kh + 64 * 20;
    uint32_t* Vh = Kl + 64 * 20;                       // [32][36] (V transposed)
    uint32_t* Vl = Vh + 32 * 36;

    const int n0 = blockIdx.x * 64;
    const int h  = blockIdx.y;
    const int b  = blockIdx.z;
    const int tid = threadIdx.x, lane = tid & 31, warp = tid >> 5;
    const int r = lane >> 2, c = lane & 3;

    for (int i = tid; i < TABLE_SZ; i += 128) tab_s[i] = g_tab[h * TABLE_SZ + i];

    // Q fragments straight from gmem (once per block)
    const float* qbase = g_qs + ((size_t)(b * NHEADS + h) * NN + n0) * HD;
    uint32_t qh[2][4], ql[2][4];
    {
        const float* q0 = qbase + (warp * 16 + r) * HD;
        const float* q1 = q0 + 8 * HD;
#pragma unroll
        for (int ks = 0; ks < 2; ks++) {
            float2 e0 = *(const float2*)&q0[ks * 16 + 2 * c];
            float2 e1 = *(const float2*)&q1[ks * 16 + 2 * c];
            float2 e2 = *(const float2*)&q0[ks * 16 + 2 * c + 8];
            float2 e3 = *(const float2*)&q1[ks * 16 + 2 * c + 8];
            bfsplit2(e0.x, e0.y, qh[ks][0], ql[ks][0]);
            bfsplit2(e1.x, e1.y, qh[ks][1], ql[ks][1]);
            bfsplit2(e2.x, e2.y, qh[ks][2], ql[ks][2]);
            bfsplit2(e3.x, e3.y, qh[ks][3], ql[ks][3]);
        }
    }

    float O[4][4] = {};
    float ml0 = -1e30f, ml1 = -1e30f, ll0 = 0.f, ll1 = 0.f;
    const float* kbase = g_kn + (size_t)(b * NHEADS + h) * NN * HD;
    const float* vbase = g_v  + (size_t)(b * NHEADS + h) * NN * HD;
    const int*   rbase = rpi + (size_t)(n0 + warp * 16) * NN;

    for (int kt = 0; kt < 16; kt++) {
        __syncthreads();   // prior tile fully consumed (kt=0: tab_s ready)
        // stage K (row-major d-pairs) and V (transposed m-pairs), hi/lo planes
#pragma unroll
        for (int i = 0; i < 4; i++) {
            int v = tid + i * 128;          // 0..511
            int m0 = (v >> 4) * 2;          // even seq row
            int d0 = (v & 15) * 2;          // even d
            const float* kp = kbase + kt * 2048 + m0 * HD + d0;
            const float* vp = vbase + kt * 2048 + m0 * HD + d0;
            float2 k0 = *(const float2*)kp;
            float2 k1 = *(const float2*)(kp + HD);
            float2 v0 = *(const float2*)vp;
            float2 v1 = *(const float2*)(vp + HD);
            uint32_t hh, ll;
            bfsplit2(k0.x, k0.y, hh, ll);
            Kh[m0 * 20 + (d0 >> 1)] = hh;        Kl[m0 * 20 + (d0 >> 1)] = ll;
            bfsplit2(k1.x, k1.y, hh, ll);
            Kh[(m0 + 1) * 20 + (d0 >> 1)] = hh;  Kl[(m0 + 1) * 20 + (d0 >> 1)] = ll;
            bfsplit2(v0.x, v1.x, hh, ll);        // pair over seq (m0, m0+1) at dim d0
            Vh[d0 * 36 + (m0 >> 1)] = hh;        Vl[d0 * 36 + (m0 >> 1)] = ll;
            bfsplit2(v0.y, v1.y, hh, ll);
            Vh[(d0 + 1) * 36 + (m0 >> 1)] = hh;  Vl[(d0 + 1) * 36 + (m0 >> 1)] = ll;
        }
        __syncthreads();

        // ---- S = Q K^T + bias ----
        float sc[8][4];
#pragma unroll
        for (int j = 0; j < 8; j++) {
            int colb = kt * 64 + j * 8 + 2 * c;
            int2 ia = *(const int2*)&rbase[(size_t)r       * NN + colb];
            int2 ib = *(const int2*)&rbase[(size_t)(r + 8) * NN + colb];
            sc[j][0] = tab_s[ia.x]; sc[j][1] = tab_s[ia.y];
            sc[j][2] = tab_s[ib.x]; sc[j][3] = tab_s[ib.y];
            int rowb = (j * 8 + r) * 20;
#pragma unroll
            for (int ks = 0; ks < 2; ks++) {
                uint32_t bh0 = Kh[rowb + ks * 8 + c], bh1 = Kh[rowb + ks * 8 + 4 + c];
                uint32_t bl0 = Kl[rowb + ks * 8 + c], bl1 = Kl[rowb + ks * 8 + 4 + c];
                mma_bf16(sc[j], qh[ks][0], qh[ks][1], qh[ks][2], qh[ks][3], bh0, bh1);
                mma_bf16(sc[j], ql[ks][0], ql[ks][1], ql[ks][2], ql[ks][3], bh0, bh1);
                mma_bf16(sc[j], qh[ks][0], qh[ks][1], qh[ks][2], qh[ks][3], bl0, bl1);
            }
        }

        // ---- online softmax (thread owns rows r and r+8 of warp tile) ----
        float mx0 = -1e30f, mx1 = -1e30f;
#pragma unroll
        for (int j = 0; j < 8; j++) {
            mx0 = fmaxf(mx0, fmaxf(sc[j][0], sc[j][1]));
            mx1 = fmaxf(mx1, fmaxf(sc[j][2], sc[j][3]));
        }
        mx0 = fmaxf(mx0, __shfl_xor_sync(0xffffffffu, mx0, 1));
        mx0 = fmaxf(mx0, __shfl_xor_sync(0xffffffffu, mx0, 2));
        mx1 = fmaxf(mx1, __shfl_xor_sync(0xffffffffu, mx1, 1));
        mx1 = fmaxf(mx1, __shfl_xor_sync(0xffffffffu, mx1, 2));
        float mn0 = fmaxf(ml0, mx0), mn1 = fmaxf(ml1, mx1);
        float a0 = __expf(ml0 - mn0), a1 = __expf(ml1 - mn1);
        float s0 = 0.f, s1 = 0.f;
        uint32_t phr[8], phr8[8], plr[8], plr8[8];
#pragma unroll
        for (int j = 0; j < 8; j++) {
            float p0 = __expf(sc[j][0] - mn0), p1 = __expf(sc[j][1] - mn0);
            float p2 = __expf(sc[j][2] - mn1), p3 = __expf(sc[j][3] - mn1);
            s0 += p0 + p1; s1 += p2 + p3;
            bfsplit2(p0, p1, phr[j],  plr[j]);
            bfsplit2(p2, p3, phr8[j], plr8[j]);
        }
        s0 += __shfl_xor_sync(0xffffffffu, s0, 1);
        s0 += __shfl_xor_sync(0xffffffffu, s0, 2);
        s1 += __shfl_xor_sync(0xffffffffu, s1, 1);
        s1 += __shfl_xor_sync(0xffffffffu, s1, 2);
        ll0 = ll0 * a0 + s0; ll1 = ll1 * a1 + s1;
        ml0 = mn0; ml1 = mn1;
#pragma unroll
        for (int jd = 0; jd < 4; jd++) {
            O[jd][0] *= a0; O[jd][1] *= a0;
            O[jd][2] *= a1; O[jd][3] *= a1;
        }

        // ---- O += P @ V  (Ph*Vh + Pl*Vh + Ph*Vl), P register-chained ----
#pragma unroll
        for (int kk = 0; kk < 4; kk++) {
            uint32_t a0h = phr[2 * kk],     a1h = phr8[2 * kk];
            uint32_t a2h = phr[2 * kk + 1], a3h = phr8[2 * kk + 1];
            uint32_t a0l = plr[2 * kk],     a1l = plr8[2 * kk];
            uint32_t a2l = plr[2 * kk + 1], a3l = plr8[2 * kk + 1];
#pragma unroll
            for (int jd = 0; jd < 4; jd++) {
                int w0 = (jd * 8 + r) * 36 + kk * 8 + c;
                uint32_t vh0 = Vh[w0], vh1 = Vh[w0 + 4];
                uint32_t vl0 = Vl[w0], vl1 = Vl[w0 + 4];
                mma_bf16(O[jd], a0h, a1h, a2h, a3h, vh0, vh1);
                mma_bf16(O[jd], a0l, a1l, a2l, a3l, vh0, vh1);
                mma_bf16(O[jd], a0h, a1h, a2h, a3h, vl0, vl1);
            }
        }
    }

    // ---- epilogue: normalize + write [b][n][h*32+d] ----
    float i0 = 1.f / ll0, i1 = 1.f / ll1;
    int row0 = n0 + warp * 16 + r;
    int row1 = row0 + 8;
#pragma unroll
    for (int jd = 0; jd < 4; jd++) {
        int col = h * HD + jd * 8 + 2 * c;
        *(float2*)&out[(size_t)(b * NN + row0) * CDIM + col] =
            make_float2(O[jd][0] * i0, O[jd][1] * i0);
        *(float2*)&out[(size_t)(b * NN + row1) * CDIM + col] =
            make_float2(O[jd][2] * i1, O[jd][3] * i1);
    }
}

// ---------------- launch ----------------------------------------------------
extern "C" void kernel_launch(void* const* d_in, const int* in_sizes, int n_in,
                              void* d_out, int out_size) {
    int s = (n_in >= 15) ? 0 : -2;
    const float* x       = (const float*)d_in[0];
    const int*   rpi     = (const int*)  d_in[3 + s];
    const float* coords  = (const float*)d_in[4 + s];
    const float* qkv_w   = (const float*)d_in[5 + s];
    const float* qkv_b   = (const float*)d_in[6 + s];
    const float* qe      = (const float*)d_in[7 + s];
    const float* temp    = (const float*)d_in[8 + s];
    const float* proj_w  = (const float*)d_in[9 + s];
    const float* proj_b  = (const float*)d_in[10 + s];
    const float* fc1w    = (const float*)d_in[11 + s];
    const float* fc1b    = (const float*)d_in[12 + s];
    const float* fc2w    = (const float*)d_in[13 + s];
    const float* fc2b    = (const float*)d_in[14 + s];
    float* out = (float*)d_out;

    float *p_qkv, *p_ao;
    cudaGetSymbolAddress((void**)&p_qkv, g_qkv);
    cudaGetSymbolAddress((void**)&p_ao,  g_ao);

    cpb_kernel<<<TABLE_SZ, 128>>>(coords, fc1w, fc1b, fc2w, fc2b);

    size_t gemm_smem = (2 * 128 * 20 + 2 * 64 * 20) * sizeof(uint32_t);   // 30.7 KB
    cudaFuncSetAttribute(gemm_tc, cudaFuncAttributeMaxDynamicSharedMemorySize, (int)gemm_smem);

    gemm_tc<<<dim3(768 / 64, (BB * NN) / 128), 256, gemm_smem>>>(
        x, qkv_w, qkv_b, p_qkv, BB * NN, 3 * CDIM, CDIM);

    {
        int warps = BB * NHEADS * NN;
        int threads = warps * 32;
        prep_kernel<<<(threads + 255) / 256, 256>>>(qe, temp);
    }

    {
        size_t smem = (3972 + 2 * 64 * 20 + 2 * 32 * 36) * sizeof(float);  // ~35.3 KB
        cudaFuncSetAttribute(attn_tc, cudaFuncAttributeMaxDynamicSharedMemorySize, (int)smem);
        attn_tc<<<dim3(16, NHEADS, BB), 128, smem>>>(rpi, p_ao);
    }

    gemm_tc<<<dim3(CDIM / 64, (BB * NN) / 128), 256, gemm_smem>>>(
        p_ao, proj_w, proj_b, out, BB * NN, CDIM, CDIM);
}

// round 5
// speedup vs baseline: 1.8216x; 1.1424x over previous
#include <cuda_runtime.h>
#include <math.h>
#include <stdint.h>

#define BB      8
#define NHEADS  8
#define HD      32
#define NN      1024
#define CDIM    256
#define TABLE_SZ 3969
#define CPBH    512

// ---------------- scratch (word layouts for MMA) ---------------------------
// Q/K: [(b*8+h)*1024 + n]*16 + dp   (dp = d-pair, low16 = even d)
// V  : [(b*8+h)*32 + d]*512 + n/2   (low16 = even n)  -- transposed
__device__ __align__(16) uint32_t g_q2h[BB * NHEADS * NN * 16];
__device__ __align__(16) uint32_t g_q2l[BB * NHEADS * NN * 16];
__device__ __align__(16) uint32_t g_kh [BB * NHEADS * NN * 16];
__device__ __align__(16) uint32_t g_kl [BB * NHEADS * NN * 16];
__device__ __align__(16) uint32_t g_vth[BB * NHEADS * HD * (NN / 2)];
__device__ __align__(16) uint32_t g_vtl[BB * NHEADS * HD * (NN / 2)];
__device__ __align__(16) uint32_t g_bias[NHEADS * NN * (NN / 2)];  // bf16x2
__device__ float g_tab[NHEADS * TABLE_SZ];
__device__ float g_ao [BB * NN * CDIM];

// ---------------- bf16 helpers --------------------------------------------
__device__ __forceinline__ uint32_t bf16x2(float lo, float hi) {
    uint32_t d;
    asm("cvt.rn.bf16x2.f32 %0, %1, %2;" : "=r"(d) : "f"(hi), "f"(lo));
    return d;
}
__device__ __forceinline__ void bfsplit2(float x0, float x1, uint32_t &hi, uint32_t &lo) {
    uint32_t h = bf16x2(x0, x1);
    float r0 = x0 - __uint_as_float(h << 16);
    float r1 = x1 - __uint_as_float(h & 0xffff0000u);
    hi = h;
    lo = bf16x2(r0, r1);
}
__device__ __forceinline__ void mma_bf16(float c[4],
                                         uint32_t a0, uint32_t a1, uint32_t a2, uint32_t a3,
                                         uint32_t b0, uint32_t b1) {
    asm volatile(
        "mma.sync.aligned.m16n8k16.row.col.f32.bf16.bf16.f32 "
        "{%0,%1,%2,%3}, {%4,%5,%6,%7}, {%8,%9}, {%0,%1,%2,%3};"
        : "+f"(c[0]), "+f"(c[1]), "+f"(c[2]), "+f"(c[3])
        : "r"(a0), "r"(a1), "r"(a2), "r"(a3), "r"(b0), "r"(b1));
}
__device__ __forceinline__ void cp16(uint32_t dst, const void* src) {
    asm volatile("cp.async.cg.shared.global [%0], [%1], 16;" :: "r"(dst), "l"(src));
}

// ---------------- CPB MLP -------------------------------------------------
__global__ void cpb_kernel(const float* __restrict__ coords,
                           const float* __restrict__ fc1w, const float* __restrict__ fc1b,
                           const float* __restrict__ fc2w, const float* __restrict__ fc2b) {
    int t = blockIdx.x;
    float c0 = coords[t * 2 + 0];
    float c1 = coords[t * 2 + 1];
    float acc[NHEADS];
#pragma unroll
    for (int h = 0; h < NHEADS; h++) acc[h] = 0.f;
    for (int j = threadIdx.x; j < CPBH; j += blockDim.x) {
        float hv = fmaxf(c0 * fc1w[j * 2] + c1 * fc1w[j * 2 + 1] + fc1b[j], 0.f);
#pragma unroll
        for (int h = 0; h < NHEADS; h++) acc[h] += hv * fc2w[h * CPBH + j];
    }
    __shared__ float red[4][NHEADS];
    int lane = threadIdx.x & 31, warp = threadIdx.x >> 5;
#pragma unroll
    for (int h = 0; h < NHEADS; h++)
        for (int o = 16; o; o >>= 1) acc[h] += __shfl_xor_sync(0xffffffffu, acc[h], o);
    if (lane == 0)
#pragma unroll
        for (int h = 0; h < NHEADS; h++) red[warp][h] = acc[h];
    __syncthreads();
    if (threadIdx.x < NHEADS) {
        float s = fc2b[threadIdx.x];
        for (int w = 0; w < 4; w++) s += red[w][threadIdx.x];
        g_tab[threadIdx.x * TABLE_SZ + t] = s;
    }
}

// ---------------- bias expand: g_bias[h][n][m/2] = bf16x2 ------------------
__global__ __launch_bounds__(256) void bias_expand(const int* __restrict__ rpi) {
    __shared__ float tab_s[TABLE_SZ];
    int h = blockIdx.x >> 6;
    int chunk = blockIdx.x & 63;
    for (int i = threadIdx.x; i < TABLE_SZ; i += 256) tab_s[i] = g_tab[h * TABLE_SZ + i];
    __syncthreads();
    for (int i = threadIdx.x; i < 16 * 512; i += 256) {
        int nl = i >> 9, mw = i & 511;
        int n = chunk * 16 + nl;
        int2 id = *(const int2*)&rpi[(size_t)n * NN + 2 * mw];
        g_bias[((size_t)h * NN + n) * 512 + mw] = bf16x2(tab_s[id.x], tab_s[id.y]);
    }
}

// ---------------- fused qkv GEMM + l2norm + split -> word layouts ----------
// 128x64 tile, 256 threads, warps 4x2, warp tile 32x32 (= one head section).
__global__ __launch_bounds__(256) void gemm_qkv_fused(
        const float* __restrict__ A, const float* __restrict__ W,
        const float* __restrict__ bias,
        const float* __restrict__ qe, const float* __restrict__ temp) {
    extern __shared__ uint32_t smg[];
    uint32_t* Ah = smg;               // [128][20]
    uint32_t* Al = Ah + 128 * 20;
    uint32_t* Wh = Al + 128 * 20;     // [64][20]
    uint32_t* Wl = Wh + 64 * 20;
    const int bm = blockIdx.y * 128, bn = blockIdx.x * 64;
    const int tid = threadIdx.x, lane = tid & 31, warp = tid >> 5;
    const int wm = (warp >> 1) * 32, wn = (warp & 1) * 32;
    const int r = lane >> 2, c = lane & 3;
    const int K = CDIM, N = 3 * CDIM;

    float acc[2][4][4];
#pragma unroll
    for (int mt = 0; mt < 2; mt++)
#pragma unroll
        for (int nt = 0; nt < 4; nt++)
#pragma unroll
            for (int q = 0; q < 4; q++) acc[mt][nt][q] = 0.f;

    for (int k0 = 0; k0 < K; k0 += 32) {
#pragma unroll
        for (int i = 0; i < 4; i++) {
            int v = tid + i * 256;
            int row = v >> 3, kq = (v & 7) * 4;
            float4 a4 = *(const float4*)&A[(size_t)(bm + row) * K + k0 + kq];
            uint32_t h, l;
            bfsplit2(a4.x, a4.y, h, l);
            Ah[row * 20 + (kq >> 1)] = h;  Al[row * 20 + (kq >> 1)] = l;
            bfsplit2(a4.z, a4.w, h, l);
            Ah[row * 20 + (kq >> 1) + 1] = h;  Al[row * 20 + (kq >> 1) + 1] = l;
        }
#pragma unroll
        for (int i = 0; i < 2; i++) {
            int v = tid + i * 256;
            int row = v >> 3, kq = (v & 7) * 4;
            float4 w4 = *(const float4*)&W[(size_t)(bn + row) * K + k0 + kq];
            uint32_t h, l;
            bfsplit2(w4.x, w4.y, h, l);
            Wh[row * 20 + (kq >> 1)] = h;  Wl[row * 20 + (kq >> 1)] = l;
            bfsplit2(w4.z, w4.w, h, l);
            Wh[row * 20 + (kq >> 1) + 1] = h;  Wl[row * 20 + (kq >> 1) + 1] = l;
        }
        __syncthreads();
#pragma unroll
        for (int kt = 0; kt < 2; kt++) {
            uint32_t ah[2][4], al[2][4];
#pragma unroll
            for (int mt = 0; mt < 2; mt++) {
                int r0 = (wm + mt * 16 + r) * 20 + kt * 8 + c;
                int r1 = r0 + 8 * 20;
                ah[mt][0] = Ah[r0];     al[mt][0] = Al[r0];
                ah[mt][1] = Ah[r1];     al[mt][1] = Al[r1];
                ah[mt][2] = Ah[r0 + 4]; al[mt][2] = Al[r0 + 4];
                ah[mt][3] = Ah[r1 + 4]; al[mt][3] = Al[r1 + 4];
            }
#pragma unroll
            for (int nt = 0; nt < 4; nt++) {
                int w0 = (wn + nt * 8 + r) * 20 + kt * 8 + c;
                uint32_t bh0 = Wh[w0], bh1 = Wh[w0 + 4];
                uint32_t bl0 = Wl[w0], bl1 = Wl[w0 + 4];
#pragma unroll
                for (int mt = 0; mt < 2; mt++) {
                    mma_bf16(acc[mt][nt], ah[mt][0], ah[mt][1], ah[mt][2], ah[mt][3], bh0, bh1);
                    mma_bf16(acc[mt][nt], al[mt][0], al[mt][1], al[mt][2], al[mt][3], bh0, bh1);
                    mma_bf16(acc[mt][nt], ah[mt][0], ah[mt][1], ah[mt][2], ah[mt][3], bl0, bl1);
                }
            }
        }
        __syncthreads();
    }

    // ---- fused epilogue: bias, per-head l2norm, split, store word layouts ----
    const int col_base = bn + wn;                 // 32-aligned; head section
    const int region = col_base >> 8;             // 0=q, 1=k, 2=v
    const int head = (col_base >> 5) & 7;
    float scale_h = 0.f, qe0[4], qe1[4];
    if (region == 0) {
        scale_h = log1pf(expf(temp[head])) * logf(1024.0f);
#pragma unroll
        for (int nt = 0; nt < 4; nt++) {
            qe0[nt] = qe[head * HD + nt * 8 + 2 * c];
            qe1[nt] = qe[head * HD + nt * 8 + 2 * c + 1];
        }
    }
#pragma unroll
    for (int mt = 0; mt < 2; mt++) {
#pragma unroll
        for (int half = 0; half < 2; half++) {
            int row = bm + wm + mt * 16 + r + half * 8;
            int bq = row >> 10, n = row & 1023;
            float v0[4], v1[4];
#pragma unroll
            for (int nt = 0; nt < 4; nt++) {
                int cg = col_base + nt * 8 + 2 * c;
                v0[nt] = acc[mt][nt][half * 2]     + bias[cg];
                v1[nt] = acc[mt][nt][half * 2 + 1] + bias[cg + 1];
            }
            if (region < 2) {
                float ss = 0.f;
#pragma unroll
                for (int nt = 0; nt < 4; nt++) ss += v0[nt] * v0[nt] + v1[nt] * v1[nt];
                ss += __shfl_xor_sync(0xffffffffu, ss, 1);
                ss += __shfl_xor_sync(0xffffffffu, ss, 2);
                float inv = 1.f / fmaxf(sqrtf(ss), 1e-12f);
                size_t base = ((size_t)(bq * 8 + head) * NN + n) * 16;
#pragma unroll
                for (int nt = 0; nt < 4; nt++) {
                    float a = v0[nt] * inv, bv = v1[nt] * inv;
                    if (region == 0) {
                        a  = (a  + qe0[nt]) * scale_h;
                        bv = (bv + qe1[nt]) * scale_h;
                    }
                    uint32_t hh, ll;
                    bfsplit2(a, bv, hh, ll);
                    size_t w = base + nt * 4 + c;
                    if (region == 0) { g_q2h[w] = hh; g_q2l[w] = ll; }
                    else             { g_kh[w]  = hh; g_kl[w]  = ll; }
                }
            } else {
                // V: pair rows (even n, odd n) via shfl_xor(4); store transposed
                size_t bh = (size_t)(bq * 8 + head);
                int np = n >> 1;
                bool evenr = ((r & 1) == 0);
#pragma unroll
                for (int nt = 0; nt < 4; nt++) {
                    float ge = __shfl_xor_sync(0xffffffffu, v0[nt], 4);
                    float go = __shfl_xor_sync(0xffffffffu, v1[nt], 4);
                    int dloc = nt * 8 + 2 * c;
                    float p0, p1; int d;
                    if (evenr) { p0 = v0[nt]; p1 = ge;     d = dloc; }
                    else       { p0 = go;     p1 = v1[nt]; d = dloc + 1; }
                    uint32_t hh, ll;
                    bfsplit2(p0, p1, hh, ll);
                    size_t w = (bh * HD + d) * 512 + np;
                    g_vth[w] = hh; g_vtl[w] = ll;
                }
            }
        }
    }
}

// ---------------- generic bf16 GEMM (proj) ---------------------------------
__global__ void __launch_bounds__(256) gemm_tc(const float* __restrict__ A,
                                               const float* __restrict__ W,
                                               const float* __restrict__ bias,
                                               float* __restrict__ C,
                                               int M, int N, int K) {
    extern __shared__ uint32_t smg[];
    uint32_t* Ah = smg;
    uint32_t* Al = Ah + 128 * 20;
    uint32_t* Wh = Al + 128 * 20;
    uint32_t* Wl = Wh + 64 * 20;
    const int bm = blockIdx.y * 128, bn = blockIdx.x * 64;
    const int tid = threadIdx.x, lane = tid & 31, warp = tid >> 5;
    const int wm = (warp >> 1) * 32, wn = (warp & 1) * 32;
    const int r = lane >> 2, c = lane & 3;

    float acc[2][4][4];
#pragma unroll
    for (int mt = 0; mt < 2; mt++)
#pragma unroll
        for (int nt = 0; nt < 4; nt++)
#pragma unroll
            for (int q = 0; q < 4; q++) acc[mt][nt][q] = 0.f;

    for (int k0 = 0; k0 < K; k0 += 32) {
#pragma unroll
        for (int i = 0; i < 4; i++) {
            int v = tid + i * 256;
            int row = v >> 3, kq = (v & 7) * 4;
            float4 a4 = *(const float4*)&A[(size_t)(bm + row) * K + k0 + kq];
            uint32_t h, l;
            bfsplit2(a4.x, a4.y, h, l);
            Ah[row * 20 + (kq >> 1)] = h;  Al[row * 20 + (kq >> 1)] = l;
            bfsplit2(a4.z, a4.w, h, l);
            Ah[row * 20 + (kq >> 1) + 1] = h;  Al[row * 20 + (kq >> 1) + 1] = l;
        }
#pragma unroll
        for (int i = 0; i < 2; i++) {
            int v = tid + i * 256;
            int row = v >> 3, kq = (v & 7) * 4;
            float4 w4 = *(const float4*)&W[(size_t)(bn + row) * K + k0 + kq];
            uint32_t h, l;
            bfsplit2(w4.x, w4.y, h, l);
            Wh[row * 20 + (kq >> 1)] = h;  Wl[row * 20 + (kq >> 1)] = l;
            bfsplit2(w4.z, w4.w, h, l);
            Wh[row * 20 + (kq >> 1) + 1] = h;  Wl[row * 20 + (kq >> 1) + 1] = l;
        }
        __syncthreads();
#pragma unroll
        for (int kt = 0; kt < 2; kt++) {
            uint32_t ah[2][4], al[2][4];
#pragma unroll
            for (int mt = 0; mt < 2; mt++) {
                int r0 = (wm + mt * 16 + r) * 20 + kt * 8 + c;
                int r1 = r0 + 8 * 20;
                ah[mt][0] = Ah[r0];     al[mt][0] = Al[r0];
                ah[mt][1] = Ah[r1];     al[mt][1] = Al[r1];
                ah[mt][2] = Ah[r0 + 4]; al[mt][2] = Al[r0 + 4];
                ah[mt][3] = Ah[r1 + 4]; al[mt][3] = Al[r1 + 4];
            }
#pragma unroll
            for (int nt = 0; nt < 4; nt++) {
                int w0 = (wn + nt * 8 + r) * 20 + kt * 8 + c;
                uint32_t bh0 = Wh[w0], bh1 = Wh[w0 + 4];
                uint32_t bl0 = Wl[w0], bl1 = Wl[w0 + 4];
#pragma unroll
                for (int mt = 0; mt < 2; mt++) {
                    mma_bf16(acc[mt][nt], ah[mt][0], ah[mt][1], ah[mt][2], ah[mt][3], bh0, bh1);
                    mma_bf16(acc[mt][nt], al[mt][0], al[mt][1], al[mt][2], al[mt][3], bh0, bh1);
                    mma_bf16(acc[mt][nt], ah[mt][0], ah[mt][1], ah[mt][2], ah[mt][3], bl0, bl1);
                }
            }
        }
        __syncthreads();
    }
#pragma unroll
    for (int mt = 0; mt < 2; mt++) {
        int row0 = bm + wm + mt * 16 + r;
        int row1 = row0 + 8;
#pragma unroll
        for (int nt = 0; nt < 4; nt++) {
            int n = bn + wn + nt * 8 + 2 * c;
            float b0 = bias[n], b1 = bias[n + 1];
            *(float2*)&C[(size_t)row0 * N + n] = make_float2(acc[mt][nt][0] + b0, acc[mt][nt][1] + b1);
            *(float2*)&C[(size_t)row1 * N + n] = make_float2(acc[mt][nt][2] + b0, acc[mt][nt][3] + b1);
        }
    }
}

// ---------------- attention: cp.async double-buffered, pure copy + MMA ------
#define ABUF 4864   // words per buffer: Kh 1280 | Kl 1280 | Vh 1152 | Vl 1152

__global__ __launch_bounds__(128, 4) void attn_tc(float* __restrict__ out) {
    extern __shared__ uint32_t smw[];

    const int n0 = blockIdx.x * 64;
    const int h  = blockIdx.y;
    const int b  = blockIdx.z;
    const int tid = threadIdx.x, lane = tid & 31, warp = tid >> 5;
    const int r = lane >> 2, c = lane & 3;
    const size_t bh = (size_t)(b * NHEADS + h);

    const uint32_t* kh_g  = g_kh  + bh * NN * 16;
    const uint32_t* kl_g  = g_kl  + bh * NN * 16;
    const uint32_t* vth_g = g_vth + bh * HD * 512;
    const uint32_t* vtl_g = g_vtl + bh * HD * 512;

    // stage-issue helper (pure 16B copies)
    auto issue = [&](int kt, int buf) {
        uint32_t s0 = (uint32_t)__cvta_generic_to_shared(smw + buf * ABUF);
#pragma unroll
        for (int i = 0; i < 4; i++) {
            int v = tid + i * 128;
            int plane = v >> 8, rem = v & 255;
            int row = rem >> 2, cq = (rem & 3) * 4;
            const uint32_t* src = (plane ? kl_g : kh_g) + (size_t)(kt * 64 + row) * 16 + cq;
            cp16(s0 + (plane * 1280 + row * 20 + cq) * 4, src);
        }
#pragma unroll
        for (int i = 0; i < 4; i++) {
            int v = tid + i * 128;
            int plane = v >> 8, rem = v & 255;
            int d = rem >> 3, cq = (rem & 7) * 4;
            const uint32_t* src = (plane ? vtl_g : vth_g) + (size_t)d * 512 + kt * 32 + cq;
            cp16(s0 + (2560 + plane * 1152 + d * 36 + cq) * 4, src);
        }
    };

    issue(0, 0);
    asm volatile("cp.async.commit_group;");

    // Q fragments (LDG overlaps with first cp.async)
    const int nr = n0 + warp * 16 + r;
    const uint32_t* qh_g = g_q2h + bh * NN * 16;
    const uint32_t* ql_g = g_q2l + bh * NN * 16;
    uint32_t qh[2][4], ql[2][4];
#pragma unroll
    for (int ks = 0; ks < 2; ks++) {
        qh[ks][0] = qh_g[(size_t)nr * 16 + ks * 8 + c];
        qh[ks][1] = qh_g[(size_t)(nr + 8) * 16 + ks * 8 + c];
        qh[ks][2] = qh_g[(size_t)nr * 16 + ks * 8 + 4 + c];
        qh[ks][3] = qh_g[(size_t)(nr + 8) * 16 + ks * 8 + 4 + c];
        ql[ks][0] = ql_g[(size_t)nr * 16 + ks * 8 + c];
        ql[ks][1] = ql_g[(size_t)(nr + 8) * 16 + ks * 8 + c];
        ql[ks][2] = ql_g[(size_t)nr * 16 + ks * 8 + 4 + c];
        ql[ks][3] = ql_g[(size_t)(nr + 8) * 16 + ks * 8 + 4 + c];
    }

    const uint32_t* b0p = g_bias + ((size_t)h * NN + nr) * 512;
    const uint32_t* b1p = b0p + 8 * 512;

    float O[4][4] = {};
    float ml0 = -1e30f, ml1 = -1e30f, ll0 = 0.f, ll1 = 0.f;

    for (int kt = 0; kt < 16; kt++) {
        __syncthreads();   // all warps done reading the buffer we write next
        if (kt < 15) {
            issue(kt + 1, (kt + 1) & 1);
            asm volatile("cp.async.commit_group;");
            asm volatile("cp.async.wait_group 1;");
        } else {
            asm volatile("cp.async.wait_group 0;");
        }
        __syncthreads();

        const uint32_t* Khb = smw + (kt & 1) * ABUF;
        const uint32_t* Klb = Khb + 1280;
        const uint32_t* Vhb = Khb + 2560;
        const uint32_t* Vlb = Khb + 3712;

        // init S with bias (coalesced bf16x2 loads)
        float sc[8][4];
#pragma unroll
        for (int j = 0; j < 8; j++) {
            uint32_t w0 = b0p[kt * 32 + j * 4 + c];
            uint32_t w1 = b1p[kt * 32 + j * 4 + c];
            sc[j][0] = __uint_as_float(w0 << 16);
            sc[j][1] = __uint_as_float(w0 & 0xffff0000u);
            sc[j][2] = __uint_as_float(w1 << 16);
            sc[j][3] = __uint_as_float(w1 & 0xffff0000u);
        }

        // ---- S += Q K^T (3-plane bf16) ----
#pragma unroll
        for (int j = 0; j < 8; j++) {
            int rowb = (j * 8 + r) * 20;
#pragma unroll
            for (int ks = 0; ks < 2; ks++) {
                uint32_t bh0 = Khb[rowb + ks * 8 + c], bh1 = Khb[rowb + ks * 8 + 4 + c];
                uint32_t bl0 = Klb[rowb + ks * 8 + c], bl1 = Klb[rowb + ks * 8 + 4 + c];
                mma_bf16(sc[j], qh[ks][0], qh[ks][1], qh[ks][2], qh[ks][3], bh0, bh1);
                mma_bf16(sc[j], ql[ks][0], ql[ks][1], ql[ks][2], ql[ks][3], bh0, bh1);
                mma_bf16(sc[j], qh[ks][0], qh[ks][1], qh[ks][2], qh[ks][3], bl0, bl1);
            }
        }

        // ---- online softmax ----
        float mx0 = -1e30f, mx1 = -1e30f;
#pragma unroll
        for (int j = 0; j < 8; j++) {
            mx0 = fmaxf(mx0, fmaxf(sc[j][0], sc[j][1]));
            mx1 = fmaxf(mx1, fmaxf(sc[j][2], sc[j][3]));
        }
        mx0 = fmaxf(mx0, __shfl_xor_sync(0xffffffffu, mx0, 1));
        mx0 = fmaxf(mx0, __shfl_xor_sync(0xffffffffu, mx0, 2));
        mx1 = fmaxf(mx1, __shfl_xor_sync(0xffffffffu, mx1, 1));
        mx1 = fmaxf(mx1, __shfl_xor_sync(0xffffffffu, mx1, 2));
        float mn0 = fmaxf(ml0, mx0), mn1 = fmaxf(ml1, mx1);
        float a0 = __expf(ml0 - mn0), a1 = __expf(ml1 - mn1);
        float s0 = 0.f, s1 = 0.f;
        uint32_t phr[8], phr8[8], plr[8], plr8[8];
#pragma unroll
        for (int j = 0; j < 8; j++) {
            float p0 = __expf(sc[j][0] - mn0), p1 = __expf(sc[j][1] - mn0);
            float p2 = __expf(sc[j][2] - mn1), p3 = __expf(sc[j][3] - mn1);
            s0 += p0 + p1; s1 += p2 + p3;
            bfsplit2(p0, p1, phr[j],  plr[j]);
            bfsplit2(p2, p3, phr8[j], plr8[j]);
        }
        s0 += __shfl_xor_sync(0xffffffffu, s0, 1);
        s0 += __shfl_xor_sync(0xffffffffu, s0, 2);
        s1 += __shfl_xor_sync(0xffffffffu, s1, 1);
        s1 += __shfl_xor_sync(0xffffffffu, s1, 2);
        ll0 = ll0 * a0 + s0; ll1 = ll1 * a1 + s1;
        ml0 = mn0; ml1 = mn1;
#pragma unroll
        for (int jd = 0; jd < 4; jd++) {
            O[jd][0] *= a0; O[jd][1] *= a0;
            O[jd][2] *= a1; O[jd][3] *= a1;
        }

        // ---- O += P @ V (register-chained P, 3-term) ----
#pragma unroll
        for (int kk = 0; kk < 4; kk++) {
            uint32_t a0h = phr[2 * kk],     a1h = phr8[2 * kk];
            uint32_t a2h = phr[2 * kk + 1], a3h = phr8[2 * kk + 1];
            uint32_t a0l = plr[2 * kk],     a1l = plr8[2 * kk];
            uint32_t a2l = plr[2 * kk + 1], a3l = plr8[2 * kk + 1];
#pragma unroll
            for (int jd = 0; jd < 4; jd++) {
                int w0 = (jd * 8 + r) * 36 + kk * 8 + c;
                uint32_t vh0 = Vhb[w0], vh1 = Vhb[w0 + 4];
                uint32_t vl0 = Vlb[w0], vl1 = Vlb[w0 + 4];
                mma_bf16(O[jd], a0h, a1h, a2h, a3h, vh0, vh1);
                mma_bf16(O[jd], a0l, a1l, a2l, a3l, vh0, vh1);
                mma_bf16(O[jd], a0h, a1h, a2h, a3h, vl0, vl1);
            }
        }
    }

    // ---- epilogue ----
    float i0 = 1.f / ll0, i1 = 1.f / ll1;
    int row0 = nr;
    int row1 = nr + 8;
#pragma unroll
    for (int jd = 0; jd < 4; jd++) {
        int col = h * HD + jd * 8 + 2 * c;
        *(float2*)&out[(size_t)(b * NN + row0) * CDIM + col] =
            make_float2(O[jd][0] * i0, O[jd][1] * i0);
        *(float2*)&out[(size_t)(b * NN + row1) * CDIM + col] =
            make_float2(O[jd][2] * i1, O[jd][3] * i1);
    }
}

// ---------------- launch ----------------------------------------------------
extern "C" void kernel_launch(void* const* d_in, const int* in_sizes, int n_in,
                              void* d_out, int out_size) {
    int s = (n_in >= 15) ? 0 : -2;
    const float* x       = (const float*)d_in[0];
    const int*   rpi     = (const int*)  d_in[3 + s];
    const float* coords  = (const float*)d_in[4 + s];
    const float* qkv_w   = (const float*)d_in[5 + s];
    const float* qkv_b   = (const float*)d_in[6 + s];
    const float* qe      = (const float*)d_in[7 + s];
    const float* temp    = (const float*)d_in[8 + s];
    const float* proj_w  = (const float*)d_in[9 + s];
    const float* proj_b  = (const float*)d_in[10 + s];
    const float* fc1w    = (const float*)d_in[11 + s];
    const float* fc1b    = (const float*)d_in[12 + s];
    const float* fc2w    = (const float*)d_in[13 + s];
    const float* fc2b    = (const float*)d_in[14 + s];
    float* out = (float*)d_out;

    float* p_ao;
    cudaGetSymbolAddress((void**)&p_ao, g_ao);

    cpb_kernel<<<TABLE_SZ, 128>>>(coords, fc1w, fc1b, fc2w, fc2b);
    bias_expand<<<NHEADS * 64, 256>>>(rpi);

    size_t gemm_smem = (2 * 128 * 20 + 2 * 64 * 20) * sizeof(uint32_t);   // 30.7 KB
    cudaFuncSetAttribute(gemm_qkv_fused, cudaFuncAttributeMaxDynamicSharedMemorySize, (int)gemm_smem);
    cudaFuncSetAttribute(gemm_tc, cudaFuncAttributeMaxDynamicSharedMemorySize, (int)gemm_smem);

    gemm_qkv_fused<<<dim3(768 / 64, (BB * NN) / 128), 256, gemm_smem>>>(
        x, qkv_w, qkv_b, qe, temp);

    {
        size_t smem = 2 * ABUF * sizeof(uint32_t);   // 38.9 KB
        cudaFuncSetAttribute(attn_tc, cudaFuncAttributeMaxDynamicSharedMemorySize, (int)smem);
        attn_tc<<<dim3(16, NHEADS, BB), 128, smem>>>(p_ao);
    }

    gemm_tc<<<dim3(CDIM / 64, (BB * NN) / 128), 256, gemm_smem>>>(
        p_ao, proj_w, proj_b, out, BB * NN, CDIM, CDIM);
}